// round 2
// baseline (speedup 1.0000x reference)
#include <cuda_runtime.h>

// ---------------- problem constants ----------------
#define H_IMG 64
#define W_IMG 64
#define C_IMG 3
#define PAD 10
#define KH 32
#define KW 32
#define LH 53                 // H + 2*PAD - KH + 1
#define NP 2809               // LH*LH patches
#define NPPAD 2816            // padded to multiple of 128
#define DDIM 3072             // C*KH*KW
#define NMEM 8192

// ---------------- scratch (device globals; no runtime allocation) ----------------
__device__ float g_patches[(size_t)NPPAD * DDIM];   // ~34.6 MB
__device__ float g_memsq[NMEM];
__device__ unsigned long long g_best[NPPAD];        // (key<<32)|col  argmin accumulator
__device__ int g_row[NP];                           // mapping[nn[p]]
__device__ float g_acc[H_IMG * W_IMG * C_IMG];      // HWC accumulation

// ---------------- helpers ----------------
__device__ __forceinline__ unsigned fkey(float f) {
    // monotonic float -> unsigned mapping (smaller float -> smaller key)
    unsigned u = __float_as_uint(f);
    return (u & 0x80000000u) ? ~u : (u | 0x80000000u);
}

__device__ __forceinline__ unsigned long long pack2(float lo, float hi) {
    unsigned long long v;
    asm("mov.b64 %0, {%1, %2};" : "=l"(v)
        : "r"(__float_as_uint(lo)), "r"(__float_as_uint(hi)));
    return v;
}

__device__ __forceinline__ void unpack2(unsigned long long v, float& lo, float& hi) {
    unsigned a, b;
    asm("mov.b64 {%0, %1}, %2;" : "=r"(a), "=r"(b) : "l"(v));
    lo = __uint_as_float(a);
    hi = __uint_as_float(b);
}

// packed fp32x2 FMA (sm_100+): d = a*b + d, lanewise on two f32
__device__ __forceinline__ void ffma2(unsigned long long& d,
                                      unsigned long long a,
                                      unsigned long long b) {
    asm("fma.rn.f32x2 %0, %1, %2, %0;" : "+l"(d) : "l"(a), "l"(b));
}

__device__ __forceinline__ unsigned long long u64min(unsigned long long a,
                                                     unsigned long long b) {
    return a < b ? a : b;
}

// ---------------- kernel 1: build patch matrix + init argmin ----------------
__global__ void k_patches(const float* __restrict__ image) {
    int p = blockIdx.x;                      // 0..NPPAD-1
    if (threadIdx.x == 0) g_best[p] = 0xFFFFFFFFFFFFFFFFULL;
    int lh = p / LH, lw = p % LH;
    bool valid = (p < NP);
    for (int k = threadIdx.x; k < DDIM; k += blockDim.x) {
        int c = k >> 10;                     // k / 1024
        int rem = k & 1023;
        int kh = rem >> 5, kw = rem & 31;
        int h = lh + kh - PAD;
        int w = lw + kw - PAD;
        float v = 0.0f;
        if (valid && (unsigned)h < (unsigned)H_IMG && (unsigned)w < (unsigned)W_IMG)
            v = image[(h * W_IMG + w) * C_IMG + c];
        g_patches[(size_t)p * DDIM + k] = v;
    }
}

// ---------------- kernel 2: mem_sq (one warp per row) ----------------
__global__ void k_memsq(const float* __restrict__ mem) {
    int row = blockIdx.x * 8 + (threadIdx.x >> 5);
    int lane = threadIdx.x & 31;
    const float* r = mem + (size_t)row * DDIM;
    float s = 0.0f;
    for (int k = lane; k < DDIM; k += 32) {
        float v = r[k];
        s += v * v;
    }
    #pragma unroll
    for (int o = 16; o; o >>= 1) s += __shfl_xor_sync(0xFFFFFFFFu, s, o);
    if (lane == 0) g_memsq[row] = s;
}

// ---------------- kernel 3: fused fp32 GEMM + argmin ----------------
#define BM 128
#define BN 128
#define BK 16

__global__ void __launch_bounds__(256) k_gemm_argmin(const float* __restrict__ Bm) {
    __shared__ float As[2][BK][BM];
    __shared__ float Bs[2][BK][BN];
    __shared__ unsigned long long sbest[BM];

    const int tid = threadIdx.x;
    const int tx = tid & 15;          // column group 0..15
    const int ty = tid >> 4;          // row group 0..15
    const int mBase = blockIdx.y * BM;
    const int nBase = blockIdx.x * BN;

    const int lrow = tid >> 2;        // 0..63
    const int lcol = (tid & 3) << 2;  // 0,4,8,12

    if (tid < BM) sbest[tid] = 0xFFFFFFFFFFFFFFFFULL;

    // accumulators: 8 rows x 4 f32x2 pairs (= 8x8 fp32)
    unsigned long long acc[8][4];
    #pragma unroll
    for (int i = 0; i < 8; i++)
        #pragma unroll
        for (int j = 0; j < 4; j++) acc[i][j] = 0ULL;  // {+0.0f,+0.0f}

    float4 aR[2], bR[2];
    // prologue: load tile 0
    #pragma unroll
    for (int s = 0; s < 2; s++) {
        int r = lrow + s * 64;
        aR[s] = *(const float4*)(g_patches + (size_t)(mBase + r) * DDIM + lcol);
        bR[s] = *(const float4*)(Bm + (size_t)(nBase + r) * DDIM + lcol);
    }
    #pragma unroll
    for (int s = 0; s < 2; s++) {
        int r = lrow + s * 64;
        As[0][lcol + 0][r] = aR[s].x; As[0][lcol + 1][r] = aR[s].y;
        As[0][lcol + 2][r] = aR[s].z; As[0][lcol + 3][r] = aR[s].w;
        Bs[0][lcol + 0][r] = bR[s].x; Bs[0][lcol + 1][r] = bR[s].y;
        Bs[0][lcol + 2][r] = bR[s].z; Bs[0][lcol + 3][r] = bR[s].w;
    }
    __syncthreads();

    const int KT = DDIM / BK;   // 192
    for (int kt = 0; kt < KT; ++kt) {
        const int cur = kt & 1;
        if (kt + 1 < KT) {
            const int kb = (kt + 1) * BK;
            #pragma unroll
            for (int s = 0; s < 2; s++) {
                int r = lrow + s * 64;
                aR[s] = *(const float4*)(g_patches + (size_t)(mBase + r) * DDIM + kb + lcol);
                bR[s] = *(const float4*)(Bm + (size_t)(nBase + r) * DDIM + kb + lcol);
            }
        }
        #pragma unroll
        for (int kk = 0; kk < BK; ++kk) {
            const float4 a0 = *(const float4*)&As[cur][kk][ty * 4];
            const float4 a1 = *(const float4*)&As[cur][kk][64 + ty * 4];
            const float4 b0 = *(const float4*)&Bs[cur][kk][tx * 4];
            const float4 b1 = *(const float4*)&Bs[cur][kk][64 + tx * 4];
            unsigned long long bp[4];
            bp[0] = pack2(b0.x, b0.y); bp[1] = pack2(b0.z, b0.w);
            bp[2] = pack2(b1.x, b1.y); bp[3] = pack2(b1.z, b1.w);
            float av[8] = {a0.x, a0.y, a0.z, a0.w, a1.x, a1.y, a1.z, a1.w};
            #pragma unroll
            for (int i = 0; i < 8; i++) {
                unsigned long long ap = pack2(av[i], av[i]);
                #pragma unroll
                for (int j = 0; j < 4; j++) ffma2(acc[i][j], ap, bp[j]);
            }
        }
        if (kt + 1 < KT) {
            const int nxt = cur ^ 1;
            #pragma unroll
            for (int s = 0; s < 2; s++) {
                int r = lrow + s * 64;
                As[nxt][lcol + 0][r] = aR[s].x; As[nxt][lcol + 1][r] = aR[s].y;
                As[nxt][lcol + 2][r] = aR[s].z; As[nxt][lcol + 3][r] = aR[s].w;
                Bs[nxt][lcol + 0][r] = bR[s].x; Bs[nxt][lcol + 1][r] = bR[s].y;
                Bs[nxt][lcol + 2][r] = bR[s].z; Bs[nxt][lcol + 3][r] = bR[s].w;
            }
        }
        __syncthreads();
    }

    // epilogue: per-row argmin of d = memsq[c] - 2*score
    #pragma unroll
    for (int i = 0; i < 8; i++) {
        int rloc = (i < 4) ? (ty * 4 + i) : (64 + ty * 4 + (i - 4));
        unsigned long long best = 0xFFFFFFFFFFFFFFFFULL;
        #pragma unroll
        for (int j = 0; j < 4; j++) {
            float lo, hi;
            unpack2(acc[i][j], lo, hi);
            int cloc = (j < 2) ? (tx * 4 + 2 * j) : (64 + tx * 4 + 2 * (j - 2));
            int c0 = nBase + cloc;
            float d0 = g_memsq[c0]     - 2.0f * lo;
            float d1 = g_memsq[c0 + 1] - 2.0f * hi;
            unsigned long long k0 = ((unsigned long long)fkey(d0) << 32) | (unsigned)c0;
            unsigned long long k1 = ((unsigned long long)fkey(d1) << 32) | (unsigned)(c0 + 1);
            best = u64min(best, u64min(k0, k1));
        }
        atomicMin(&sbest[rloc], best);
    }
    __syncthreads();
    if (tid < BM) atomicMin(&g_best[mBase + tid], sbest[tid]);
}

// ---------------- kernel 4: nn -> mapping gather ----------------
__global__ void k_nnmap(const int* __restrict__ mapping) {
    int p = blockIdx.x * blockDim.x + threadIdx.x;
    if (p < NP) {
        unsigned nn = (unsigned)(g_best[p] & 0xFFFFFFFFu);
        g_row[p] = mapping[nn];
    }
}

// ---------------- kernel 5: fold (gather) ----------------
__global__ void __launch_bounds__(256) k_fold(const float* __restrict__ mem2) {
    const int w = blockIdx.x;
    const int h = blockIdx.y;
    const int hp = h + PAD, wp = w + PAD;
    const int kh0 = max(0, hp - (LH - 1)), kh1 = min(KH - 1, hp);
    const int kw0 = max(0, wp - (LH - 1)), kw1 = min(KW - 1, wp);
    const int nkh = kh1 - kh0 + 1;
    const int nkw = kw1 - kw0 + 1;
    const int cnt = nkh * nkw;

    float s0 = 0.0f, s1 = 0.0f, s2 = 0.0f;
    for (int t = threadIdx.x; t < cnt; t += blockDim.x) {
        int kh = kh0 + t / nkw;
        int kw = kw0 + t % nkw;
        int lh = hp - kh, lw = wp - kw;
        int row = g_row[lh * LH + lw];
        const float* base = mem2 + (size_t)row * DDIM + kh * KW + kw;
        s0 += base[0];
        s1 += base[1024];
        s2 += base[2048];
    }
    #pragma unroll
    for (int o = 16; o; o >>= 1) {
        s0 += __shfl_xor_sync(0xFFFFFFFFu, s0, o);
        s1 += __shfl_xor_sync(0xFFFFFFFFu, s1, o);
        s2 += __shfl_xor_sync(0xFFFFFFFFu, s2, o);
    }
    __shared__ float red[8][3];
    int wid = threadIdx.x >> 5, lane = threadIdx.x & 31;
    if (lane == 0) { red[wid][0] = s0; red[wid][1] = s1; red[wid][2] = s2; }
    __syncthreads();
    if (threadIdx.x < 3) {
        float s = 0.0f;
        #pragma unroll
        for (int i = 0; i < 8; i++) s += red[i][threadIdx.x];
        g_acc[(h * W_IMG + w) * C_IMG + threadIdx.x] = s;
    }
}

// ---------------- kernel 6: global max + normalize ----------------
__global__ void k_finalize(float* __restrict__ out) {
    __shared__ float sm[256];
    const int N = H_IMG * W_IMG * C_IMG;
    float m = -3.402823466e38f;
    for (int i = threadIdx.x; i < N; i += 256) m = fmaxf(m, g_acc[i]);
    sm[threadIdx.x] = m;
    __syncthreads();
    for (int s = 128; s; s >>= 1) {
        if (threadIdx.x < s) sm[threadIdx.x] = fmaxf(sm[threadIdx.x], sm[threadIdx.x + s]);
        __syncthreads();
    }
    float mv = sm[0];
    for (int i = threadIdx.x; i < N; i += 256) out[i] = g_acc[i] / mv;
}

// ---------------- launch ----------------
extern "C" void kernel_launch(void* const* d_in, const int* in_sizes, int n_in,
                              void* d_out, int out_size) {
    const float* image   = (const float*)d_in[0];
    const float* mem     = (const float*)d_in[1];
    const float* mem2    = (const float*)d_in[2];
    const int*   mapping = (const int*)d_in[3];

    k_patches<<<NPPAD, 256>>>(image);
    k_memsq<<<NMEM / 8, 256>>>(mem);
    k_gemm_argmin<<<dim3(NMEM / BN, NPPAD / BM), 256>>>(mem);
    k_nnmap<<<(NP + 255) / 256, 256>>>(mapping);
    k_fold<<<dim3(W_IMG, H_IMG), 256>>>(mem2);
    k_finalize<<<1, 256>>>((float*)d_out);
}

// round 5
// speedup vs baseline: 2.2017x; 2.2017x over previous
#include <cuda_runtime.h>
#include <cstdint>

// ---------------- problem constants ----------------
#define H_IMG 64
#define W_IMG 64
#define C_IMG 3
#define PAD 10
#define KH 32
#define KW 32
#define LH 53                 // H + 2*PAD - KH + 1
#define NP 2809               // LH*LH patches
#define NPPAD 2816            // multiple of 128
#define DDIM 3072             // C*KH*KW
#define NMEM 8192
#define MARGIN 8.0f

// GEMM tiling
#define BM 128
#define BN 128
#define BK 16
#define NKT (DDIM / BK)       // 192
#define KPAD (BK + 4)         // padded smem row (words)

// ---------------- scratch (device globals; no runtime allocation) ----------------
__device__ float    g_patches[(size_t)NPPAD * DDIM];    // exact (rescore)
__device__ uint32_t g_patchesr[(size_t)NPPAD * DDIM];   // tf32-rounded (GEMM)
__device__ uint32_t g_memr[(size_t)NMEM * DDIM];        // tf32-rounded mem
__device__ float    g_memsq[NMEM];
__device__ unsigned long long g_best[NPPAD];            // (fkey<<32)|col approx argmin
__device__ float    g_dist[(size_t)NPPAD * NMEM];       // approx distances
__device__ int      g_row[NP];
__device__ float    g_acc[H_IMG * W_IMG * C_IMG];

// ---------------- helpers ----------------
__device__ __forceinline__ unsigned fkey(float f) {
    unsigned u = __float_as_uint(f);
    return (u & 0x80000000u) ? ~u : (u | 0x80000000u);
}
__device__ __forceinline__ float finv(unsigned k) {
    return __uint_as_float((k & 0x80000000u) ? (k ^ 0x80000000u) : ~k);
}
__device__ __forceinline__ uint32_t f2tf32(float f) {
    uint32_t r;
    asm("cvt.rna.tf32.f32 %0, %1;" : "=r"(r) : "f"(f));
    return r;
}
__device__ __forceinline__ uint32_t smem_u32(const void* p) {
    uint32_t a;
    asm("{ .reg .u64 t; cvta.to.shared.u64 t, %1; cvt.u32.u64 %0, t; }" : "=r"(a) : "l"(p));
    return a;
}
__device__ __forceinline__ void cpa16(uint32_t dst, const void* src) {
    asm volatile("cp.async.cg.shared.global [%0], [%1], 16;\n" :: "r"(dst), "l"(src));
}
#define CP_COMMIT() asm volatile("cp.async.commit_group;" ::: "memory")
#define CP_WAIT(n)  asm volatile("cp.async.wait_group %0;" :: "n"(n) : "memory")

__device__ __forceinline__ void mma_tf32(float& c0, float& c1, float& c2, float& c3,
                                         uint32_t a0, uint32_t a1, uint32_t a2, uint32_t a3,
                                         uint32_t b0, uint32_t b1) {
    asm volatile(
        "mma.sync.aligned.m16n8k8.row.col.f32.tf32.tf32.f32 "
        "{%0,%1,%2,%3}, {%4,%5,%6,%7}, {%8,%9}, {%0,%1,%2,%3};"
        : "+f"(c0), "+f"(c1), "+f"(c2), "+f"(c3)
        : "r"(a0), "r"(a1), "r"(a2), "r"(a3), "r"(b0), "r"(b1));
}

// ---------------- kernel 1: build patch matrix (exact + tf32) ----------------
__global__ void k_patches(const float* __restrict__ image) {
    int p = blockIdx.x;
    if (threadIdx.x == 0) g_best[p] = 0xFFFFFFFFFFFFFFFFULL;
    int lh = p / LH, lw = p % LH;
    bool valid = (p < NP);
    for (int k = threadIdx.x; k < DDIM; k += blockDim.x) {
        int c = k >> 10;
        int rem = k & 1023;
        int kh = rem >> 5, kw = rem & 31;
        int h = lh + kh - PAD;
        int w = lw + kw - PAD;
        float v = 0.0f;
        if (valid && (unsigned)h < (unsigned)H_IMG && (unsigned)w < (unsigned)W_IMG)
            v = image[(h * W_IMG + w) * C_IMG + c];
        size_t idx = (size_t)p * DDIM + k;
        g_patches[idx] = v;
        g_patchesr[idx] = f2tf32(v);
    }
}

// ---------------- kernel 2: mem -> tf32 copy + mem_sq ----------------
__global__ void k_memcvt(const float* __restrict__ mem) {
    int row = blockIdx.x * 8 + (threadIdx.x >> 5);
    int lane = threadIdx.x & 31;
    const float* r = mem + (size_t)row * DDIM;
    uint32_t* o = g_memr + (size_t)row * DDIM;
    float s = 0.0f;
    for (int k = lane; k < DDIM; k += 32) {
        float v = r[k];
        s += v * v;
        o[k] = f2tf32(v);
    }
    #pragma unroll
    for (int off = 16; off; off >>= 1) s += __shfl_xor_sync(0xFFFFFFFFu, s, off);
    if (lane == 0) g_memsq[row] = s;
}

// ---------------- kernel 3: mma.sync tf32 GEMM + approx distances ----------------
// static smem: 2 stages x (A[128][20] + B[128][20]) words = 40KB (+1KB sbest)
__global__ void __launch_bounds__(256, 2) k_gemm_mma() {
    __shared__ uint32_t smem_buf[2][2][BM * KPAD];
    __shared__ unsigned long long sbest[BM];

    const int tid = threadIdx.x;
    const int wid = tid >> 5;
    const int lane = tid & 31;
    const int g = lane >> 2;          // group 0..7
    const int tg = lane & 3;          // thread-in-group 0..3
    const int warpM = wid >> 1;       // 0..3  (M 32 each)
    const int warpN = wid & 1;        // 0..1  (N 64 each)
    const int mBase = blockIdx.y * BM;
    const int nBase = blockIdx.x * BN;

    if (tid < BM) sbest[tid] = 0xFFFFFFFFFFFFFFFFULL;

    const uint32_t sA[2] = { smem_u32(&smem_buf[0][0][0]), smem_u32(&smem_buf[1][0][0]) };
    const uint32_t sB[2] = { smem_u32(&smem_buf[0][1][0]), smem_u32(&smem_buf[1][1][0]) };

    float acc[2][8][4];
    #pragma unroll
    for (int mt = 0; mt < 2; mt++)
        #pragma unroll
        for (int nt = 0; nt < 8; nt++)
            #pragma unroll
            for (int i = 0; i < 4; i++) acc[mt][nt][i] = 0.0f;

    // each thread copies 2 A chunks + 2 B chunks (16B each) per stage
    // chunk index i in 0..511: row = i>>2, seg = i&3
    auto load_stage = [&](int kt, int buf) {
        const int kb = kt * BK;
        #pragma unroll
        for (int t = 0; t < 2; t++) {
            int i = tid + 256 * t;
            int row = i >> 2, seg = i & 3;
            uint32_t doff = (uint32_t)(row * KPAD + seg * 4) * 4u;
            cpa16(sA[buf] + doff, g_patchesr + (size_t)(mBase + row) * DDIM + kb + seg * 4);
            cpa16(sB[buf] + doff, g_memr    + (size_t)(nBase + row) * DDIM + kb + seg * 4);
        }
        CP_COMMIT();
    };

    load_stage(0, 0);

    for (int kt = 0; kt < NKT; ++kt) {
        const int cur = kt & 1;
        if (kt + 1 < NKT) {
            load_stage(kt + 1, cur ^ 1);
            CP_WAIT(1);
        } else {
            CP_WAIT(0);
        }
        __syncthreads();

        const uint32_t* A = &smem_buf[cur][0][0];
        const uint32_t* B = &smem_buf[cur][1][0];
        #pragma unroll
        for (int ks = 0; ks < BK / 8; ++ks) {
            const int kc = ks * 8;
            // B fragments: 8 n-tiles x 2 regs
            uint32_t bf[8][2];
            #pragma unroll
            for (int nt = 0; nt < 8; nt++) {
                const uint32_t* bp = B + (warpN * 64 + nt * 8 + g) * KPAD + kc + tg;
                bf[nt][0] = bp[0];
                bf[nt][1] = bp[4];
            }
            #pragma unroll
            for (int mt = 0; mt < 2; mt++) {
                const uint32_t* ap = A + (warpM * 32 + mt * 16 + g) * KPAD + kc + tg;
                uint32_t a0 = ap[0];
                uint32_t a1 = ap[8 * KPAD];
                uint32_t a2 = ap[4];
                uint32_t a3 = ap[8 * KPAD + 4];
                #pragma unroll
                for (int nt = 0; nt < 8; nt++)
                    mma_tf32(acc[mt][nt][0], acc[mt][nt][1], acc[mt][nt][2], acc[mt][nt][3],
                             a0, a1, a2, a3, bf[nt][0], bf[nt][1]);
            }
        }
        __syncthreads();
    }

    // ---- epilogue: d = memsq - 2*score -> g_dist + approx argmin ----
    #pragma unroll
    for (int mt = 0; mt < 2; mt++) {
        const int rloc0 = warpM * 32 + mt * 16 + g;      // rows rloc0, rloc0+8
        unsigned long long best0 = 0xFFFFFFFFFFFFFFFFULL;
        unsigned long long best1 = 0xFFFFFFFFFFFFFFFFULL;
        #pragma unroll
        for (int nt = 0; nt < 8; nt++) {
            const int c0 = nBase + warpN * 64 + nt * 8 + tg * 2;
            const float q0 = g_memsq[c0], q1 = g_memsq[c0 + 1];
            float d00 = q0 - 2.0f * acc[mt][nt][0];
            float d01 = q1 - 2.0f * acc[mt][nt][1];
            float d10 = q0 - 2.0f * acc[mt][nt][2];
            float d11 = q1 - 2.0f * acc[mt][nt][3];
            unsigned long long k00 = ((unsigned long long)fkey(d00) << 32) | (unsigned)c0;
            unsigned long long k01 = ((unsigned long long)fkey(d01) << 32) | (unsigned)(c0 + 1);
            unsigned long long k10 = ((unsigned long long)fkey(d10) << 32) | (unsigned)c0;
            unsigned long long k11 = ((unsigned long long)fkey(d11) << 32) | (unsigned)(c0 + 1);
            best0 = min(best0, min(k00, k01));
            best1 = min(best1, min(k10, k11));
            float* dr0 = g_dist + (size_t)(mBase + rloc0) * NMEM + c0;
            float* dr1 = g_dist + (size_t)(mBase + rloc0 + 8) * NMEM + c0;
            *(float2*)dr0 = make_float2(d00, d01);
            *(float2*)dr1 = make_float2(d10, d11);
        }
        atomicMin(&sbest[rloc0], best0);
        atomicMin(&sbest[rloc0 + 8], best1);
    }
    __syncthreads();
    if (tid < BM) atomicMin(&g_best[mBase + tid], sbest[tid]);
}

// ---------------- kernel 4: candidate scan + exact fp32 rescore ----------------
__global__ void __launch_bounds__(256) k_rescore(const float* __restrict__ mem,
                                                 const int* __restrict__ mapping) {
    const int p = blockIdx.x;
    const int tid = threadIdx.x;
    __shared__ int s_cnt;
    __shared__ int s_cand[128];
    __shared__ float s_red[256];
    __shared__ unsigned long long s_best;
    if (tid == 0) { s_cnt = 0; s_best = 0xFFFFFFFFFFFFFFFFULL; }
    __syncthreads();

    const float thr = finv((unsigned)(g_best[p] >> 32)) + MARGIN;
    const float* drow = g_dist + (size_t)p * NMEM;
    for (int c = tid; c < NMEM; c += 256) {
        if (drow[c] <= thr) {
            int i = atomicAdd(&s_cnt, 1);
            if (i < 128) s_cand[i] = c;
        }
    }
    __syncthreads();
    const int n = min(s_cnt, 128);
    const float* pr = g_patches + (size_t)p * DDIM;
    for (int i = 0; i < n; i++) {
        const int c = s_cand[i];
        const float* mr = mem + (size_t)c * DDIM;
        float s = 0.0f;
        for (int k = tid; k < DDIM; k += 256) s += pr[k] * mr[k];
        s_red[tid] = s;
        __syncthreads();
        for (int st = 128; st; st >>= 1) {
            if (tid < st) s_red[tid] += s_red[tid + st];
            __syncthreads();
        }
        if (tid == 0) {
            float dex = g_memsq[c] - 2.0f * s_red[0];
            unsigned long long key = ((unsigned long long)fkey(dex) << 32) | (unsigned)c;
            if (key < s_best) s_best = key;
        }
        __syncthreads();
    }
    if (tid == 0) g_row[p] = mapping[(unsigned)(s_best & 0xFFFFFFFFu)];
}

// ---------------- kernel 5: fold (gather) ----------------
__global__ void __launch_bounds__(256) k_fold(const float* __restrict__ mem2) {
    const int w = blockIdx.x;
    const int h = blockIdx.y;
    const int hp = h + PAD, wp = w + PAD;
    const int kh0 = max(0, hp - (LH - 1)), kh1 = min(KH - 1, hp);
    const int kw0 = max(0, wp - (LH - 1)), kw1 = min(KW - 1, wp);
    const int nkh = kh1 - kh0 + 1;
    const int nkw = kw1 - kw0 + 1;
    const int cnt = nkh * nkw;

    float s0 = 0.0f, s1 = 0.0f, s2 = 0.0f;
    for (int t = threadIdx.x; t < cnt; t += blockDim.x) {
        int kh = kh0 + t / nkw;
        int kw = kw0 + t % nkw;
        int lh = hp - kh, lw = wp - kw;
        int row = g_row[lh * LH + lw];
        const float* base = mem2 + (size_t)row * DDIM + kh * KW + kw;
        s0 += base[0];
        s1 += base[1024];
        s2 += base[2048];
    }
    #pragma unroll
    for (int o = 16; o; o >>= 1) {
        s0 += __shfl_xor_sync(0xFFFFFFFFu, s0, o);
        s1 += __shfl_xor_sync(0xFFFFFFFFu, s1, o);
        s2 += __shfl_xor_sync(0xFFFFFFFFu, s2, o);
    }
    __shared__ float red[8][3];
    int wid = threadIdx.x >> 5, lane = threadIdx.x & 31;
    if (lane == 0) { red[wid][0] = s0; red[wid][1] = s1; red[wid][2] = s2; }
    __syncthreads();
    if (threadIdx.x < 3) {
        float s = 0.0f;
        #pragma unroll
        for (int i = 0; i < 8; i++) s += red[i][threadIdx.x];
        g_acc[(h * W_IMG + w) * C_IMG + threadIdx.x] = s;
    }
}

// ---------------- kernel 6: global max + normalize ----------------
__global__ void k_finalize(float* __restrict__ out) {
    __shared__ float sm[256];
    const int N = H_IMG * W_IMG * C_IMG;
    float m = -3.402823466e38f;
    for (int i = threadIdx.x; i < N; i += 256) m = fmaxf(m, g_acc[i]);
    sm[threadIdx.x] = m;
    __syncthreads();
    for (int s = 128; s; s >>= 1) {
        if (threadIdx.x < s) sm[threadIdx.x] = fmaxf(sm[threadIdx.x], sm[threadIdx.x + s]);
        __syncthreads();
    }
    float mv = sm[0];
    for (int i = threadIdx.x; i < N; i += 256) out[i] = g_acc[i] / mv;
}

// ---------------- launch ----------------
extern "C" void kernel_launch(void* const* d_in, const int* in_sizes, int n_in,
                              void* d_out, int out_size) {
    const float* image   = (const float*)d_in[0];
    const float* mem     = (const float*)d_in[1];
    const float* mem2    = (const float*)d_in[2];
    const int*   mapping = (const int*)d_in[3];

    k_patches<<<NPPAD, 256>>>(image);
    k_memcvt<<<NMEM / 8, 256>>>(mem);
    k_gemm_mma<<<dim3(NMEM / BN, NPPAD / BM), 256>>>();
    k_rescore<<<NP, 256>>>(mem, mapping);
    k_fold<<<dim3(W_IMG, H_IMG), 256>>>(mem2);
    k_finalize<<<1, 256>>>((float*)d_out);
}

// round 6
// speedup vs baseline: 3.9928x; 1.8135x over previous
#include <cuda_runtime.h>
#include <cuda_bf16.h>
#include <cstdint>

// ---------------- problem constants ----------------
#define H_IMG 64
#define W_IMG 64
#define C_IMG 3
#define PAD 10
#define KH 32
#define KW 32
#define LH 53                 // H + 2*PAD - KH + 1
#define NP 2809               // LH*LH patches
#define NPPAD 2816            // multiple of 128
#define DDIM 3072             // C*KH*KW
#define NMEM 8192
#define MARGIN 8.0f

// GEMM tiling (bf16, m16n8k16)
#define BM 128
#define BN 128
#define BK 32                 // bf16 elems per k-tile
#define NKT (DDIM / BK)       // 96
#define RPW 20                // smem row pitch in words (40 bf16 = 32 + 8 pad)

// ---------------- scratch (device globals; no runtime allocation) ----------------
__device__ float          g_patches[(size_t)NPPAD * DDIM];   // exact (rescore)
__device__ __nv_bfloat16  g_patchesh[(size_t)NPPAD * DDIM];  // bf16 (GEMM)
__device__ __nv_bfloat16  g_memh[(size_t)NMEM * DDIM];       // bf16 mem
__device__ float          g_memsq[NMEM];
__device__ unsigned long long g_best[NPPAD];                 // (fkey<<32)|col approx argmin
__device__ float          g_dist[(size_t)NPPAD * NMEM];      // approx distances
__device__ int            g_row[NP];
__device__ float          g_acc[H_IMG * W_IMG * C_IMG];

// ---------------- helpers ----------------
__device__ __forceinline__ unsigned fkey(float f) {
    unsigned u = __float_as_uint(f);
    return (u & 0x80000000u) ? ~u : (u | 0x80000000u);
}
__device__ __forceinline__ float finv(unsigned k) {
    return __uint_as_float((k & 0x80000000u) ? (k ^ 0x80000000u) : ~k);
}
__device__ __forceinline__ uint32_t smem_u32(const void* p) {
    uint32_t a;
    asm("{ .reg .u64 t; cvta.to.shared.u64 t, %1; cvt.u32.u64 %0, t; }" : "=r"(a) : "l"(p));
    return a;
}
__device__ __forceinline__ void cpa16(uint32_t dst, const void* src) {
    asm volatile("cp.async.cg.shared.global [%0], [%1], 16;\n" :: "r"(dst), "l"(src));
}
#define CP_COMMIT() asm volatile("cp.async.commit_group;" ::: "memory")
#define CP_WAIT(n)  asm volatile("cp.async.wait_group %0;" :: "n"(n) : "memory")

__device__ __forceinline__ void mma_bf16(float& c0, float& c1, float& c2, float& c3,
                                         uint32_t a0, uint32_t a1, uint32_t a2, uint32_t a3,
                                         uint32_t b0, uint32_t b1) {
    asm volatile(
        "mma.sync.aligned.m16n8k16.row.col.f32.bf16.bf16.f32 "
        "{%0,%1,%2,%3}, {%4,%5,%6,%7}, {%8,%9}, {%0,%1,%2,%3};"
        : "+f"(c0), "+f"(c1), "+f"(c2), "+f"(c3)
        : "r"(a0), "r"(a1), "r"(a2), "r"(a3), "r"(b0), "r"(b1));
}

// ---------------- kernel 1: build patch matrix (exact + bf16) ----------------
__global__ void k_patches(const float* __restrict__ image) {
    int p = blockIdx.x;
    if (threadIdx.x == 0) g_best[p] = 0xFFFFFFFFFFFFFFFFULL;
    int lh = p / LH, lw = p % LH;
    bool valid = (p < NP);
    for (int k = threadIdx.x; k < DDIM; k += blockDim.x) {
        int c = k >> 10;
        int rem = k & 1023;
        int kh = rem >> 5, kw = rem & 31;
        int h = lh + kh - PAD;
        int w = lw + kw - PAD;
        float v = 0.0f;
        if (valid && (unsigned)h < (unsigned)H_IMG && (unsigned)w < (unsigned)W_IMG)
            v = image[(h * W_IMG + w) * C_IMG + c];
        size_t idx = (size_t)p * DDIM + k;
        g_patches[idx] = v;
        g_patchesh[idx] = __float2bfloat16(v);
    }
}

// ---------------- kernel 2: mem -> bf16 copy + mem_sq ----------------
__global__ void k_memcvt(const float* __restrict__ mem) {
    int row = blockIdx.x * 8 + (threadIdx.x >> 5);
    int lane = threadIdx.x & 31;
    const float* r = mem + (size_t)row * DDIM;
    __nv_bfloat16* o = g_memh + (size_t)row * DDIM;
    float s = 0.0f;
    for (int k = lane; k < DDIM; k += 32) {
        float v = r[k];
        s += v * v;
        o[k] = __float2bfloat16(v);
    }
    #pragma unroll
    for (int off = 16; off; off >>= 1) s += __shfl_xor_sync(0xFFFFFFFFu, s, off);
    if (lane == 0) g_memsq[row] = s;
}

// ---------------- kernel 3: mma.sync bf16 GEMM + approx distances ----------------
// static smem: 2 stages x (A[128][20w] + B[128][20w]) = 40KB (+1KB sbest)
__global__ void __launch_bounds__(256, 2) k_gemm_mma() {
    __shared__ uint32_t smem_buf[2][2][BM * RPW];
    __shared__ unsigned long long sbest[BM];

    const int tid = threadIdx.x;
    const int wid = tid >> 5;
    const int lane = tid & 31;
    const int g = lane >> 2;          // group 0..7
    const int tg = lane & 3;          // thread-in-group 0..3
    const int warpM = wid >> 1;       // 0..3  (M 32 each)
    const int warpN = wid & 1;        // 0..1  (N 64 each)
    const int mBase = blockIdx.y * BM;
    const int nBase = blockIdx.x * BN;

    if (tid < BM) sbest[tid] = 0xFFFFFFFFFFFFFFFFULL;

    const uint32_t sA[2] = { smem_u32(&smem_buf[0][0][0]), smem_u32(&smem_buf[1][0][0]) };
    const uint32_t sB[2] = { smem_u32(&smem_buf[0][1][0]), smem_u32(&smem_buf[1][1][0]) };

    float acc[2][8][4];
    #pragma unroll
    for (int mt = 0; mt < 2; mt++)
        #pragma unroll
        for (int nt = 0; nt < 8; nt++)
            #pragma unroll
            for (int i = 0; i < 4; i++) acc[mt][nt][i] = 0.0f;

    // per stage: each matrix = 128 rows x 64B = 512 x 16B chunks; 2 per thread
    // chunk i: row = i>>2, seg = i&3; dst word = row*RPW + seg*4
    auto load_stage = [&](int kt, int buf) {
        const int kb = kt * BK;
        #pragma unroll
        for (int t = 0; t < 2; t++) {
            int i = tid + 256 * t;
            int row = i >> 2, seg = i & 3;
            uint32_t doff = (uint32_t)(row * RPW + seg * 4) * 4u;
            cpa16(sA[buf] + doff, g_patchesh + (size_t)(mBase + row) * DDIM + kb + seg * 8);
            cpa16(sB[buf] + doff, g_memh    + (size_t)(nBase + row) * DDIM + kb + seg * 8);
        }
        CP_COMMIT();
    };

    load_stage(0, 0);

    for (int kt = 0; kt < NKT; ++kt) {
        const int cur = kt & 1;
        if (kt + 1 < NKT) {
            load_stage(kt + 1, cur ^ 1);
            CP_WAIT(1);
        } else {
            CP_WAIT(0);
        }
        __syncthreads();

        const uint32_t* A = &smem_buf[cur][0][0];
        const uint32_t* B = &smem_buf[cur][1][0];
        #pragma unroll
        for (int ks = 0; ks < BK / 16; ++ks) {
            const int kw = ks * 8;    // word offset (16 bf16)
            // B fragments: 8 n-tiles x 2 regs
            uint32_t bf[8][2];
            #pragma unroll
            for (int nt = 0; nt < 8; nt++) {
                const uint32_t* bp = B + (warpN * 64 + nt * 8 + g) * RPW + kw;
                bf[nt][0] = bp[tg];
                bf[nt][1] = bp[tg + 4];
            }
            #pragma unroll
            for (int mt = 0; mt < 2; mt++) {
                const uint32_t* ap = A + (warpM * 32 + mt * 16 + g) * RPW + kw;
                uint32_t a0 = ap[tg];
                uint32_t a1 = ap[8 * RPW + tg];
                uint32_t a2 = ap[tg + 4];
                uint32_t a3 = ap[8 * RPW + tg + 4];
                #pragma unroll
                for (int nt = 0; nt < 8; nt++)
                    mma_bf16(acc[mt][nt][0], acc[mt][nt][1], acc[mt][nt][2], acc[mt][nt][3],
                             a0, a1, a2, a3, bf[nt][0], bf[nt][1]);
            }
        }
        __syncthreads();
    }

    // ---- epilogue: d = memsq - 2*score -> g_dist + approx argmin ----
    #pragma unroll
    for (int mt = 0; mt < 2; mt++) {
        const int rloc0 = warpM * 32 + mt * 16 + g;      // rows rloc0, rloc0+8
        unsigned long long best0 = 0xFFFFFFFFFFFFFFFFULL;
        unsigned long long best1 = 0xFFFFFFFFFFFFFFFFULL;
        #pragma unroll
        for (int nt = 0; nt < 8; nt++) {
            const int c0 = nBase + warpN * 64 + nt * 8 + tg * 2;
            const float q0 = g_memsq[c0], q1 = g_memsq[c0 + 1];
            float d00 = q0 - 2.0f * acc[mt][nt][0];
            float d01 = q1 - 2.0f * acc[mt][nt][1];
            float d10 = q0 - 2.0f * acc[mt][nt][2];
            float d11 = q1 - 2.0f * acc[mt][nt][3];
            unsigned long long k00 = ((unsigned long long)fkey(d00) << 32) | (unsigned)c0;
            unsigned long long k01 = ((unsigned long long)fkey(d01) << 32) | (unsigned)(c0 + 1);
            unsigned long long k10 = ((unsigned long long)fkey(d10) << 32) | (unsigned)c0;
            unsigned long long k11 = ((unsigned long long)fkey(d11) << 32) | (unsigned)(c0 + 1);
            best0 = min(best0, min(k00, k01));
            best1 = min(best1, min(k10, k11));
            float* dr0 = g_dist + (size_t)(mBase + rloc0) * NMEM + c0;
            float* dr1 = g_dist + (size_t)(mBase + rloc0 + 8) * NMEM + c0;
            *(float2*)dr0 = make_float2(d00, d01);
            *(float2*)dr1 = make_float2(d10, d11);
        }
        atomicMin(&sbest[rloc0], best0);
        atomicMin(&sbest[rloc0 + 8], best1);
    }
    __syncthreads();
    if (tid < BM) atomicMin(&g_best[mBase + tid], sbest[tid]);
}

// ---------------- kernel 4: candidate scan + exact fp32 rescore ----------------
__global__ void __launch_bounds__(256) k_rescore(const float* __restrict__ mem,
                                                 const int* __restrict__ mapping) {
    const int p = blockIdx.x;
    const int tid = threadIdx.x;
    __shared__ int s_cnt;
    __shared__ int s_cand[128];
    __shared__ float s_red[256];
    __shared__ unsigned long long s_best;
    if (tid == 0) { s_cnt = 0; s_best = 0xFFFFFFFFFFFFFFFFULL; }
    __syncthreads();

    const float thr = finv((unsigned)(g_best[p] >> 32)) + MARGIN;
    const float* drow = g_dist + (size_t)p * NMEM;
    for (int c = tid; c < NMEM; c += 256) {
        if (drow[c] <= thr) {
            int i = atomicAdd(&s_cnt, 1);
            if (i < 128) s_cand[i] = c;
        }
    }
    __syncthreads();
    const int n = min(s_cnt, 128);
    const float* pr = g_patches + (size_t)p * DDIM;
    for (int i = 0; i < n; i++) {
        const int c = s_cand[i];
        const float* mr = mem + (size_t)c * DDIM;
        float s = 0.0f;
        for (int k = tid; k < DDIM; k += 256) s += pr[k] * mr[k];
        s_red[tid] = s;
        __syncthreads();
        for (int st = 128; st; st >>= 1) {
            if (tid < st) s_red[tid] += s_red[tid + st];
            __syncthreads();
        }
        if (tid == 0) {
            float dex = g_memsq[c] - 2.0f * s_red[0];
            unsigned long long key = ((unsigned long long)fkey(dex) << 32) | (unsigned)c;
            if (key < s_best) s_best = key;
        }
        __syncthreads();
    }
    if (tid == 0) g_row[p] = mapping[(unsigned)(s_best & 0xFFFFFFFFu)];
}

// ---------------- kernel 5: fold (gather) ----------------
__global__ void __launch_bounds__(256) k_fold(const float* __restrict__ mem2) {
    const int w = blockIdx.x;
    const int h = blockIdx.y;
    const int hp = h + PAD, wp = w + PAD;
    const int kh0 = max(0, hp - (LH - 1)), kh1 = min(KH - 1, hp);
    const int kw0 = max(0, wp - (LH - 1)), kw1 = min(KW - 1, wp);
    const int nkh = kh1 - kh0 + 1;
    const int nkw = kw1 - kw0 + 1;
    const int cnt = nkh * nkw;

    float s0 = 0.0f, s1 = 0.0f, s2 = 0.0f;
    for (int t = threadIdx.x; t < cnt; t += blockDim.x) {
        int kh = kh0 + t / nkw;
        int kw = kw0 + t % nkw;
        int lh = hp - kh, lw = wp - kw;
        int row = g_row[lh * LH + lw];
        const float* base = mem2 + (size_t)row * DDIM + kh * KW + kw;
        s0 += base[0];
        s1 += base[1024];
        s2 += base[2048];
    }
    #pragma unroll
    for (int o = 16; o; o >>= 1) {
        s0 += __shfl_xor_sync(0xFFFFFFFFu, s0, o);
        s1 += __shfl_xor_sync(0xFFFFFFFFu, s1, o);
        s2 += __shfl_xor_sync(0xFFFFFFFFu, s2, o);
    }
    __shared__ float red[8][3];
    int wid = threadIdx.x >> 5, lane = threadIdx.x & 31;
    if (lane == 0) { red[wid][0] = s0; red[wid][1] = s1; red[wid][2] = s2; }
    __syncthreads();
    if (threadIdx.x < 3) {
        float s = 0.0f;
        #pragma unroll
        for (int i = 0; i < 8; i++) s += red[i][threadIdx.x];
        g_acc[(h * W_IMG + w) * C_IMG + threadIdx.x] = s;
    }
}

// ---------------- kernel 6: global max + normalize ----------------
__global__ void k_finalize(float* __restrict__ out) {
    __shared__ float sm[256];
    const int N = H_IMG * W_IMG * C_IMG;
    float m = -3.402823466e38f;
    for (int i = threadIdx.x; i < N; i += 256) m = fmaxf(m, g_acc[i]);
    sm[threadIdx.x] = m;
    __syncthreads();
    for (int s = 128; s; s >>= 1) {
        if (threadIdx.x < s) sm[threadIdx.x] = fmaxf(sm[threadIdx.x], sm[threadIdx.x + s]);
        __syncthreads();
    }
    float mv = sm[0];
    for (int i = threadIdx.x; i < N; i += 256) out[i] = g_acc[i] / mv;
}

// ---------------- launch ----------------
extern "C" void kernel_launch(void* const* d_in, const int* in_sizes, int n_in,
                              void* d_out, int out_size) {
    const float* image   = (const float*)d_in[0];
    const float* mem     = (const float*)d_in[1];
    const float* mem2    = (const float*)d_in[2];
    const int*   mapping = (const int*)d_in[3];

    k_patches<<<NPPAD, 256>>>(image);
    k_memcvt<<<NMEM / 8, 256>>>(mem);
    k_gemm_mma<<<dim3(NMEM / BN, NPPAD / BM), 256>>>();
    k_rescore<<<NP, 256>>>(mem, mapping);
    k_fold<<<dim3(W_IMG, H_IMG), 256>>>(mem2);
    k_finalize<<<1, 256>>>((float*)d_out);
}